// round 2
// baseline (speedup 1.0000x reference)
#include <cuda_runtime.h>
#include <cstdint>

// Problem constants
#define NB     512          // batch n
#define LFULL  257          // L
#define HD     256          // h (feature dim)
#define LOUT   256          // l = L-1
#define KDIM   512          // 2*h
#define HID    256          // hidden
#define NLAB   50
#define NLABP  64           // padded

#define BM       64         // tokens per CTA
#define BK       32         // k-chunk
#define NCHUNK   (KDIM / BK)   // 16
#define THREADS  256
#define NTOK     (NB * LOUT)   // 131072
#define NBLK     (NTOK / BM)   // 2048

// __device__ scratch (allocation-free rule)
__device__ float g_W1T[KDIM * HID];      // [k][o]  (512 x 256)
__device__ float g_W2T[HID * NLABP];     // [k][j]  (256 x 64, j>=50 zero)
__device__ int   g_heads64;

// SMEM layout (bytes):
//   region1 [0, 131072):
//     phase1: A2 dup-pairs (u64[64*32] = 16KB) @0 ; B (f32[32*256] = 32KB) @16384
//     phase2: hid dup-pairs (u64[64*256] = 128KB) @0
//   w2t   @131072  (f32[256*64] = 64KB)
//   b1    @196608  (f32[256])
//   b2    @197632  (f32[64])
//   rows  @197888  (int[128])
#define SMEM_BYTES 198400

__global__ void prep_kernel(const float* __restrict__ W1,
                            const float* __restrict__ W2,
                            const void*  __restrict__ heads)
{
    int idx = blockIdx.x * blockDim.x + threadIdx.x;
    if (idx < KDIM * HID) {
        int h = idx >> 8;          // / HID
        int o = idx & (HID - 1);
        g_W1T[idx] = W1[o * KDIM + h];
    } else if (idx < KDIM * HID + HID * NLABP) {
        int i2 = idx - KDIM * HID;
        int k = i2 >> 6;
        int j = i2 & (NLABP - 1);
        g_W2T[i2] = (j < NLAB) ? W2[j * HID + k] : 0.0f;
    }
    if (idx == 0) {
        // Detect heads dtype: int64 => every odd 32-bit word is 0 (values < 257).
        const unsigned* h32 = (const unsigned*)heads;
        int is64 = 1;
        for (int i = 1; i < 128; i += 2) is64 &= (h32[i] == 0u);
        g_heads64 = is64;
    }
}

__device__ __forceinline__ unsigned long long dup_f32(float v) {
    unsigned long long d;
    asm("mov.b64 %0, {%1, %1};" : "=l"(d) : "r"(__float_as_uint(v)));
    return d;
}
__device__ __forceinline__ void unpack2(unsigned long long x, float& a, float& b) {
    unsigned lo, hi;
    asm("mov.b64 {%0, %1}, %2;" : "=r"(lo), "=r"(hi) : "l"(x));
    a = __uint_as_float(lo);
    b = __uint_as_float(hi);
}
__device__ __forceinline__ void fma2(unsigned long long& acc,
                                     unsigned long long a,
                                     unsigned long long b) {
    asm("fma.rn.f32x2 %0, %1, %2, %0;" : "+l"(acc) : "l"(a), "l"(b));
}

__global__ __launch_bounds__(THREADS, 1)
void label_kernel(const float* __restrict__ feat,
                  const void*  __restrict__ heads,
                  const float* __restrict__ b1,
                  const float* __restrict__ b2,
                  float*       __restrict__ out)
{
    extern __shared__ unsigned char smem_raw[];
    unsigned long long* A2_s   = (unsigned long long*)(smem_raw);           // phase1
    float*              B_s    = (float*)(smem_raw + 16384);                // phase1
    unsigned long long* hid2_s = (unsigned long long*)(smem_raw);           // phase2
    float*              w2t_s  = (float*)(smem_raw + 131072);
    float*              b1_s   = (float*)(smem_raw + 196608);
    float*              b2_s   = (float*)(smem_raw + 197632);
    int*                rows_s = (int*)(smem_raw + 197888);

    const int tid  = threadIdx.x;
    const int lane = tid & 31;
    const int wy   = tid >> 5;            // 0..7
    const int t0   = blockIdx.x * BM;

    // ---------------- preload ----------------
    {
        float4* wdst = (float4*)w2t_s;
        const float4* wsrc = (const float4*)g_W2T;
        #pragma unroll
        for (int i = 0; i < (HID * NLABP / 4) / THREADS; ++i)   // 16 iters
            wdst[tid + THREADS * i] = wsrc[tid + THREADS * i];
    }
    if (tid < HID)   b1_s[tid] = b1[tid];
    if (tid < NLABP) b2_s[tid] = (tid < NLAB) ? b2[tid] : 0.0f;
    if (tid < BM) {
        int t = t0 + tid;
        int n = t >> 8;
        int l = t & 255;
        rows_s[tid * 2] = n * LFULL + l + 1;
        int hv;
        if (g_heads64) hv = (int)((const long long*)heads)[t];
        else           hv = ((const int*)heads)[t];
        rows_s[tid * 2 + 1] = n * LFULL + hv;
    }
    __syncthreads();

    // ---------------- GEMM1: hid = relu(cat @ W1^T + b1) ----------------
    unsigned long long acc[8][4];
    #pragma unroll
    for (int r = 0; r < 8; ++r)
        #pragma unroll
        for (int c = 0; c < 4; ++c) acc[r][c] = 0ull;

    for (int kb = 0; kb < NCHUNK; ++kb) {
        const int side = kb >> 3;                  // 0: dependent, 1: head
        const int col0 = (kb * BK) & (HD - 1);

        // load A tile (dup pairs)
        #pragma unroll
        for (int i = 0; i < 8; ++i) {
            int m = wy * 8 + i;
            int row = rows_s[m * 2 + side];
            float v = feat[(size_t)row * HD + col0 + lane];
            A2_s[m * BK + lane] = dup_f32(v);
        }
        // load B tile (coalesced from transposed W1)
        {
            const float4* Bg4 = (const float4*)(g_W1T + kb * BK * HID);
            float4* Bs4 = (float4*)B_s;
            #pragma unroll
            for (int i = 0; i < 8; ++i)
                Bs4[tid + THREADS * i] = Bg4[tid + THREADS * i];
        }
        __syncthreads();

        const unsigned long long* Bu = (const unsigned long long*)B_s;
        #pragma unroll
        for (int k = 0; k < BK; ++k) {
            unsigned long long bv[4];
            const unsigned long long* Brow = Bu + k * (HID / 2);
            #pragma unroll
            for (int c = 0; c < 4; ++c) bv[c] = Brow[c * 32 + lane];
            #pragma unroll
            for (int r = 0; r < 8; ++r) {
                unsigned long long a2 = A2_s[(wy * 8 + r) * BK + k];
                #pragma unroll
                for (int c = 0; c < 4; ++c) fma2(acc[r][c], a2, bv[c]);
            }
        }
        __syncthreads();
    }

    // epilogue: bias + relu, store dup-pairs (overwrites A/B region)
    #pragma unroll
    for (int r = 0; r < 8; ++r) {
        int m = wy * 8 + r;
        #pragma unroll
        for (int c = 0; c < 4; ++c) {
            int o = c * 64 + lane * 2;
            float v0, v1;
            unpack2(acc[r][c], v0, v1);
            v0 = fmaxf(v0 + b1_s[o], 0.0f);
            v1 = fmaxf(v1 + b1_s[o + 1], 0.0f);
            hid2_s[m * HID + o]     = dup_f32(v0);
            hid2_s[m * HID + o + 1] = dup_f32(v1);
        }
    }
    __syncthreads();

    // ---------------- GEMM2: out = hid @ W2^T + b2 ----------------
    unsigned long long acc2[8];
    #pragma unroll
    for (int r = 0; r < 8; ++r) acc2[r] = 0ull;

    const unsigned long long* W2u = (const unsigned long long*)w2t_s; // [k][32]
    #pragma unroll 4
    for (int k = 0; k < HID; k += 2) {
        unsigned long long w0 = W2u[k * 32 + lane];
        unsigned long long w1 = W2u[k * 32 + 32 + lane];
        #pragma unroll
        for (int r = 0; r < 8; ++r) {
            const ulonglong2 h =
                *reinterpret_cast<const ulonglong2*>(&hid2_s[(wy * 8 + r) * HID + k]);
            fma2(acc2[r], h.x, w0);
            fma2(acc2[r], h.y, w1);
        }
    }

    const int j = lane * 2;
    if (j < NLAB) {
        float bb0 = b2_s[j], bb1 = b2_s[j + 1];
        #pragma unroll
        for (int r = 0; r < 8; ++r) {
            int m = wy * 8 + r;
            float v0, v1;
            unpack2(acc2[r], v0, v1);
            float2 res = make_float2(v0 + bb0, v1 + bb1);
            *reinterpret_cast<float2*>(out + (size_t)(t0 + m) * NLAB + j) = res;
        }
    }
}

extern "C" void kernel_launch(void* const* d_in, const int* in_sizes, int n_in,
                              void* d_out, int out_size)
{
    const float* feat  = (const float*)d_in[0];
    const void*  heads = d_in[1];
    // d_in[2] = masks (all ones, not used by reference output)
    const float* W1    = (const float*)d_in[3];
    const float* b1    = (const float*)d_in[4];
    const float* W2    = (const float*)d_in[5];
    const float* b2    = (const float*)d_in[6];
    float* out = (float*)d_out;

    prep_kernel<<<(KDIM * HID + HID * NLABP + 255) / 256, 256>>>(W1, W2, heads);

    cudaFuncSetAttribute(label_kernel,
                         cudaFuncAttributeMaxDynamicSharedMemorySize, SMEM_BYTES);
    label_kernel<<<NBLK, THREADS, SMEM_BYTES>>>(feat, heads, b1, b2, out);
}

// round 4
// speedup vs baseline: 5.7187x; 5.7187x over previous
#include <cuda_runtime.h>
#include <cstdint>

#define NBATCH  512
#define LFULL   257
#define HD      256
#define KDIM    512
#define HID     256
#define NLAB    50

#define MT      128
#define THREADS 256
#define NBLK    1024           // 131072 / 128

// strides (floats)
#define SA  36                 // A/B tile row stride (32 + 4 pad)
#define SH  260                // hid / W2 row stride (256 + 4 pad)

// ---- SMEM layout (bytes) ----
#define A0OFF   0              // A stage0: 128*36*4 = 18432
#define A1OFF   18432
#define BS0OFF  36864          // B stage0: 256*36*4 = 36864
#define BS1OFF  73728
// phase 2 (after GEMM1): hid 128*260*4 = 133120 @ 0
#define W2SOFF  133120         // 64*260*4 = 66560 -> ends 199680 (no overlap w/ A/B)
#define BB1OFF  199680         // 256 f32
#define BB2OFF  200704         // 64 f32
#define ROWSOFF 200960         // 128*2 int
#define SMEM_BYTES 201984

__device__ float g_W1R[HID * KDIM];   // W1 rounded to tf32, layout [o][h] (natural)
__device__ float g_W2R[64 * HID];     // W2 rounded, padded to 64 rows
__device__ int   g_heads64;

__device__ __forceinline__ uint32_t smem_u32(const void* p) {
    uint32_t a;
    asm("{ .reg .u64 t; cvta.to.shared.u64 t, %1; cvt.u32.u64 %0, t; }" : "=r"(a) : "l"(p));
    return a;
}
__device__ __forceinline__ uint32_t f2tf(float f) {
    uint32_t r;
    asm("cvt.rna.tf32.f32 %0, %1;" : "=r"(r) : "f"(f));
    return r;
}

#define CP16(dst, src) \
    asm volatile("cp.async.cg.shared.global [%0], [%1], 16;" :: "r"(dst), "l"(src))
#define CPCOMMIT() asm volatile("cp.async.commit_group;" ::: "memory")
#define CPWAIT1()  asm volatile("cp.async.wait_group 1;" ::: "memory")
#define CPWAIT0()  asm volatile("cp.async.wait_group 0;" ::: "memory")

#define MMA8(c, a, b0v, b1v) \
    asm volatile("mma.sync.aligned.m16n8k8.row.col.f32.tf32.tf32.f32 " \
        "{%0,%1,%2,%3}, {%4,%5,%6,%7}, {%8,%9}, {%0,%1,%2,%3};" \
        : "+f"((c)[0]), "+f"((c)[1]), "+f"((c)[2]), "+f"((c)[3]) \
        : "r"((a)[0]), "r"((a)[1]), "r"((a)[2]), "r"((a)[3]), \
          "r"(b0v), "r"(b1v))

__global__ void prep_kernel(const float* __restrict__ W1,
                            const float* __restrict__ W2,
                            const void*  __restrict__ heads)
{
    int idx = blockIdx.x * 256 + threadIdx.x;
    if (idx < HID * KDIM) {
        g_W1R[idx] = __uint_as_float(f2tf(W1[idx]));
    } else if (idx < HID * KDIM + 64 * HID) {
        int i2 = idx - HID * KDIM;
        int n = i2 >> 8, k = i2 & 255;
        g_W2R[i2] = (n < NLAB) ? __uint_as_float(f2tf(W2[n * HID + k])) : 0.0f;
    }
    if (idx == 0) {
        // int64 heads => every odd 32-bit word zero (values < 257)
        const unsigned* h = (const unsigned*)heads;
        int is64 = 1;
        for (int i = 1; i < 128; i += 2) is64 &= (h[i] == 0u);
        g_heads64 = is64;
    }
}

__global__ __launch_bounds__(THREADS, 1)
void label_kernel(const float* __restrict__ feat,
                  const void*  __restrict__ heads,
                  const float* __restrict__ b1,
                  const float* __restrict__ b2,
                  float*       __restrict__ out)
{
    extern __shared__ __align__(1024) unsigned char smem[];
    const uint32_t sb = smem_u32(smem);

    float* b1_s   = (float*)(smem + BB1OFF);
    float* b2_s   = (float*)(smem + BB2OFF);
    int*   rows_s = (int*)(smem + ROWSOFF);

    const int tid  = threadIdx.x;
    const int lane = tid & 31;
    const int wid  = tid >> 5;
    const int mg   = wid >> 2;            // 0..1  (m group of 64 rows)
    const int ng   = wid & 3;             // 0..3  (n group of 64 cols)
    const int t0   = blockIdx.x * MT;
    const int qr   = lane >> 2;           // 0..7
    const int qc   = lane & 3;            // 0..3

    if (tid < MT) {
        int t = t0 + tid;
        int n = t >> 8, l = t & 255;
        rows_s[tid * 2] = n * LFULL + l + 1;
        int hv = g_heads64 ? (int)((const long long*)heads)[t]
                           : ((const int*)heads)[t];
        rows_s[tid * 2 + 1] = n * LFULL + hv;
    }
    b1_s[tid] = b1[tid];
    if (tid < 64) b2_s[tid] = (tid < NLAB) ? b2[tid] : 0.0f;
    __syncthreads();

    // ---- W2 tile -> SMEM (own cp.async group, completes by first wait) ----
    {
        #pragma unroll
        for (int i = 0; i < 16; ++i) {
            int idx = i * THREADS + tid;
            int n = idx >> 6, c4 = idx & 63;
            CP16(sb + W2SOFF + n * (SH * 4) + c4 * 16, g_W2R + n * HID + c4 * 4);
        }
        CPCOMMIT();
    }

    auto issue_chunk = [&](int c, int buf) {
        const int side = c >> 3;
        const int col0 = (c & 7) * 32;
        const uint32_t abase = sb + (buf ? A1OFF : A0OFF);
        #pragma unroll
        for (int i = 0; i < 4; ++i) {
            int idx = i * THREADS + tid;
            int r = idx >> 3, c4 = idx & 7;
            const float* src = feat + (size_t)rows_s[r * 2 + side] * HD + col0 + c4 * 4;
            CP16(abase + r * (SA * 4) + c4 * 16, src);
        }
        const uint32_t bbase = sb + (buf ? BS1OFF : BS0OFF);
        const float* wb = g_W1R + c * 32;
        #pragma unroll
        for (int i = 0; i < 8; ++i) {
            int idx = i * THREADS + tid;
            int n = idx >> 3, c4 = idx & 7;
            CP16(bbase + n * (SA * 4) + c4 * 16, wb + n * KDIM + c4 * 4);
        }
    };

    float acc[4][8][4];
    #pragma unroll
    for (int i = 0; i < 4; ++i)
        #pragma unroll
        for (int j = 0; j < 8; ++j)
            #pragma unroll
            for (int q = 0; q < 4; ++q) acc[i][j][q] = 0.0f;

    issue_chunk(0, 0);
    CPCOMMIT();

    // ---- GEMM1 mainloop ----
    for (int c = 0; c < 16; ++c) {
        const int buf = c & 1;
        if (c < 15) { issue_chunk(c + 1, buf ^ 1); CPCOMMIT(); CPWAIT1(); }
        else        { CPWAIT0(); }
        __syncthreads();

        const float* As = (const float*)(smem + (buf ? A1OFF : A0OFF));
        const float* Bs = (const float*)(smem + (buf ? BS1OFF : BS0OFF));
        #pragma unroll
        for (int ks = 0; ks < 4; ++ks) {
            const int k0 = ks * 8 + qc;
            uint32_t a[4][4];
            #pragma unroll
            for (int i = 0; i < 4; ++i) {
                const int base = (mg * 64 + i * 16 + qr) * SA + k0;
                a[i][0] = f2tf(As[base]);
                a[i][1] = f2tf(As[base + 8 * SA]);
                a[i][2] = f2tf(As[base + 4]);
                a[i][3] = f2tf(As[base + 8 * SA + 4]);
            }
            #pragma unroll
            for (int j = 0; j < 8; ++j) {
                const int nb = (ng * 64 + j * 8 + qr) * SA + k0;
                uint32_t b0v = __float_as_uint(Bs[nb]);
                uint32_t b1v = __float_as_uint(Bs[nb + 4]);
                #pragma unroll
                for (int i = 0; i < 4; ++i)
                    MMA8(acc[i][j], a[i], b0v, b1v);
            }
        }
        __syncthreads();
    }

    // ---- epilogue1: relu(acc + b1) -> hid SMEM as tf32 bits ----
    {
        float* hid = (float*)smem;
        #pragma unroll
        for (int i = 0; i < 4; ++i) {
            const int row0 = mg * 64 + i * 16 + qr;
            #pragma unroll
            for (int j = 0; j < 8; ++j) {
                const int col = ng * 64 + j * 8 + 2 * qc;
                uint2 v01, v23;
                v01.x = f2tf(fmaxf(acc[i][j][0] + b1_s[col], 0.0f));
                v01.y = f2tf(fmaxf(acc[i][j][1] + b1_s[col + 1], 0.0f));
                v23.x = f2tf(fmaxf(acc[i][j][2] + b1_s[col], 0.0f));
                v23.y = f2tf(fmaxf(acc[i][j][3] + b1_s[col + 1], 0.0f));
                *(uint2*)(hid + row0 * SH + col)       = v01;
                *(uint2*)(hid + (row0 + 8) * SH + col) = v23;
            }
        }
    }
    __syncthreads();

    // ---- GEMM2: out[128,50] = hid[128,256] @ W2^T ----
    float acc2[4][2][4];
    #pragma unroll
    for (int i = 0; i < 4; ++i)
        #pragma unroll
        for (int j = 0; j < 2; ++j)
            #pragma unroll
            for (int q = 0; q < 4; ++q) acc2[i][j][q] = 0.0f;

    {
        const float* Hs = (const float*)smem;
        const float* Ws = (const float*)(smem + W2SOFF);
        #pragma unroll 8
        for (int ks = 0; ks < 32; ++ks) {
            const int k0 = ks * 8 + qc;
            uint32_t a[4][4];
            #pragma unroll
            for (int i = 0; i < 4; ++i) {
                const int base = (mg * 64 + i * 16 + qr) * SH + k0;
                a[i][0] = __float_as_uint(Hs[base]);
                a[i][1] = __float_as_uint(Hs[base + 8 * SH]);
                a[i][2] = __float_as_uint(Hs[base + 4]);
                a[i][3] = __float_as_uint(Hs[base + 8 * SH + 4]);
            }
            #pragma unroll
            for (int j = 0; j < 2; ++j) {
                const int nb = (ng * 16 + j * 8 + qr) * SH + k0;
                uint32_t b0v = __float_as_uint(Ws[nb]);
                uint32_t b1v = __float_as_uint(Ws[nb + 4]);
                #pragma unroll
                for (int i = 0; i < 4; ++i)
                    MMA8(acc2[i][j], a[i], b0v, b1v);
            }
        }
    }

    // ---- output ----
    #pragma unroll
    for (int i = 0; i < 4; ++i) {
        const int row0 = mg * 64 + i * 16 + qr;
        #pragma unroll
        for (int j = 0; j < 2; ++j) {
            const int col = ng * 16 + j * 8 + 2 * qc;
            if (col < NLAB) {
                const float bb0 = b2_s[col], bb1 = b2_s[col + 1];
                float2 v0, v1;
                v0.x = acc2[i][j][0] + bb0; v0.y = acc2[i][j][1] + bb1;
                v1.x = acc2[i][j][2] + bb0; v1.y = acc2[i][j][3] + bb1;
                *(float2*)(out + (size_t)(t0 + row0) * NLAB + col)     = v0;
                *(float2*)(out + (size_t)(t0 + row0 + 8) * NLAB + col) = v1;
            }
        }
    }
}

extern "C" void kernel_launch(void* const* d_in, const int* in_sizes, int n_in,
                              void* d_out, int out_size)
{
    const float* feat  = (const float*)d_in[0];
    const void*  heads = d_in[1];
    // d_in[2] = masks (all ones; no effect on output)
    const float* W1    = (const float*)d_in[3];
    const float* b1    = (const float*)d_in[4];
    const float* W2    = (const float*)d_in[5];
    const float* b2    = (const float*)d_in[6];
    float* out = (float*)d_out;

    prep_kernel<<<(HID * KDIM + 64 * HID + 255) / 256, 256>>>(W1, W2, heads);

    cudaFuncSetAttribute(label_kernel,
                         cudaFuncAttributeMaxDynamicSharedMemorySize, SMEM_BYTES);
    label_kernel<<<NBLK, THREADS, SMEM_BYTES>>>(feat, heads, b1, b2, out);
}